// round 14
// baseline (speedup 1.0000x reference)
#include <cuda_runtime.h>
#include <cuda_bf16.h>
#include <cuda_fp16.h>
#include <cstdint>

#define DINLINE __device__ __forceinline__

// ---------------------------------------------------------------------------
// Problem constants
// ---------------------------------------------------------------------------
constexpr int NTOK  = 8192;   // B*S tokens
constexpr int IN    = 4096;
constexpr int OUT   = 4096;
constexpr int POOLS = 128;

constexpr int BK = 64;        // 16-bit elems per k-chunk -> 128B rows

constexpr float WSCALE     = 1024.0f;   // weight prescale (w0 and wr)
constexpr float INV_WSCALE = 1.0f / 1024.0f;

// Router ambiguity threshold in scaled-logit units (logits carry x1024 from
// wr prescale; per-logit fp16 error sigma ~= 0.9 in these units).
constexpr float RTHRESH = 52.0f;

// ---------------------------------------------------------------------------
// Device scratch (static __device__ globals only — no runtime allocation)
// ---------------------------------------------------------------------------
__device__ __align__(1024) __half g_xh  [(size_t)NTOK * IN];    // fp16(x)
__device__ __align__(1024) __half g_wh  [(size_t)OUT * IN];     // fp16(1024*w0)
__device__ __align__(1024) __half g_wrh [(size_t)POOLS * IN];   // fp16(1024*wr)
__device__ __align__(1024) __half g_svhh[(size_t)POOLS * IN];   // fp16(svh)
__device__ float g_dotv[(size_t)NTOK * 2];
__device__ int   g_idxv[(size_t)NTOK * 2];

// ---------------------------------------------------------------------------
// Portable PTX helpers (plain sm_103 target — no tcgen05)
// ---------------------------------------------------------------------------
DINLINE uint32_t smem_u32(const void* p) {
    uint32_t a;
    asm("{ .reg .u64 t; cvta.to.shared.u64 t, %1; cvt.u32.u64 %0, t; }" : "=r"(a) : "l"(p));
    return a;
}

// 128B-row swizzle: 16B-chunk index (bits 4..6) ^= low 3 bits of row (bits 7..9)
#define SWZ128(o) ((o) ^ (((o) >> 3) & 0x70))

#define CP_ASYNC16(saddr, gptr) \
    asm volatile("cp.async.cg.shared.global [%0], [%1], 16;" :: "r"(saddr), "l"(gptr))
#define CP_COMMIT() asm volatile("cp.async.commit_group;" ::: "memory")

template <int N>
DINLINE void cp_wait() { asm volatile("cp.async.wait_group %0;" :: "n"(N) : "memory"); }

DINLINE void ldsm_x4(uint32_t* r, uint32_t addr) {
    asm volatile("ldmatrix.sync.aligned.m8n8.x4.shared.b16 {%0,%1,%2,%3}, [%4];"
                 : "=r"(r[0]), "=r"(r[1]), "=r"(r[2]), "=r"(r[3]) : "r"(addr));
}

DINLINE void mma16816_f16(float* d, const uint32_t* a, uint32_t b0, uint32_t b1) {
    asm volatile(
        "mma.sync.aligned.m16n8k16.row.col.f32.f16.f16.f32 "
        "{%0,%1,%2,%3}, {%4,%5,%6,%7}, {%8,%9}, {%0,%1,%2,%3};"
        : "+f"(d[0]), "+f"(d[1]), "+f"(d[2]), "+f"(d[3])
        : "r"(a[0]), "r"(a[1]), "r"(a[2]), "r"(a[3]), "r"(b0), "r"(b1));
}

DINLINE uint32_t pack_h2(float a, float b) {
    __half2 t = __floats2half2_rn(a, b);
    return *(uint32_t*)&t;
}

// ---------------------------------------------------------------------------
// Kernel 0a: x -> fp16 ; wr -> fp16(1024*wr) ; svh -> fp16.
// ---------------------------------------------------------------------------
constexpr int XBLK = 1024, RBLK = 8, SBLK = 8;

__global__ void __launch_bounds__(256)
split_xw_kernel(const float4* __restrict__ x4, const float4* __restrict__ wr4,
                const float4* __restrict__ svh4) {
    const int bid = blockIdx.x;
    if (bid < XBLK) {
        const int n4 = NTOK * IN / 4;
        const int stride = XBLK * 256;
        uint2* f2 = (uint2*)g_xh;
        for (int i = bid * 256 + threadIdx.x; i < n4; i += stride) {
            float4 v = x4[i];
            f2[i] = make_uint2(pack_h2(v.x, v.y), pack_h2(v.z, v.w));
        }
    } else if (bid < XBLK + RBLK) {
        const int n4 = POOLS * IN / 4;
        const int stride = RBLK * 256;
        uint2* f2 = (uint2*)g_wrh;
        for (int i = (bid - XBLK) * 256 + threadIdx.x; i < n4; i += stride) {
            float4 v = wr4[i];
            f2[i] = make_uint2(pack_h2(v.x * WSCALE, v.y * WSCALE),
                               pack_h2(v.z * WSCALE, v.w * WSCALE));
        }
    } else {
        const int n4 = POOLS * IN / 4;
        const int stride = SBLK * 256;
        uint2* f2 = (uint2*)g_svhh;
        for (int i = (bid - XBLK - RBLK) * 256 + threadIdx.x; i < n4; i += stride) {
            float4 v = svh4[i];
            f2[i] = make_uint2(pack_h2(v.x, v.y), pack_h2(v.z, v.w));
        }
    }
}

// Kernel 0b: w0 -> fp16(WSCALE*w0). Runs on stream2, overlapped with ROUTER
// (compute-bound) rather than with the DRAM-bound split_xw.
__global__ void __launch_bounds__(256)
split_w_kernel(const float4* __restrict__ w4) {
    const int n4 = OUT * IN / 4;
    const int stride = gridDim.x * 256;
    uint2* h2 = (uint2*)g_wh;
    for (int i = blockIdx.x * 256 + threadIdx.x; i < n4; i += stride) {
        float4 v = w4[i];
        h2[i] = make_uint2(pack_h2(v.x * WSCALE, v.y * WSCALE),
                           pack_h2(v.z * WSCALE, v.w * WSCALE));
    }
}

// ---------------------------------------------------------------------------
// GEMM: out = x @ W^T, single-segment fp16, K = 4096 (64 chunks).
//   MAIN=false: router logits (BM=64, BN=128). Epilogue: fp16 top-2 with
//               margin test; ambiguous tokens re-scored with exact fp32 dots;
//               then fused per-token dual dot(xh, svh16[sel0/1]).
//   MAIN=true : main GEMM (BM=128, BN=256); epilogue: *1/1024 + b0 +
//               rank-one expert combine.
// 8 warps = 2(m) x 4(n); cp.async 4-stage pipeline, two chunks resident;
// fragment double-buffering with cross-chunk ldsm lookahead.
//   p0 = (MAIN ? b0 : x_fp32), p1 = (MAIN ? u : wr_fp32)
// ---------------------------------------------------------------------------
template <int TBM, int TBN, int NSTG, bool MAIN>
__global__ void __launch_bounds__(256, 1)
gemm_kernel(const float* __restrict__ p0, const float* __restrict__ p1,
            float* __restrict__ out) {
    static_assert(NSTG >= 3, "need two chunks resident");
    constexpr int NTH = 256;
    constexpr int WMN = 2, WNN = 4;
    constexpr int WM  = TBM / WMN;
    constexpr int WN  = TBN / WNN;
    constexpr int MT  = WM / 16;
    constexpr int NT2 = WN / 16;
    constexpr int NT8 = WN / 8;
    constexpr int A_B = TBM * 128;
    constexpr int B_B = TBN * 128;
    constexpr int STG = A_B + B_B;
    constexpr int NCH = IN / BK;          // 64

    extern __shared__ __align__(1024) char smem[];
    const uint32_t smem_base = smem_u32(smem);

    const int tid    = threadIdx.x;
    const int wid    = tid >> 5;
    const int lane   = tid & 31;
    const int warp_m = wid & 1;
    const int warp_n = wid >> 1;

    // group-swizzled CTA rasterization (L2 reuse)
    constexpr int GM = 16;
    const int num_n = MAIN ? (OUT / TBN) : 1;
    const int per_group = GM * num_n;
    const int id = blockIdx.x;
    const int m_tile = (id / per_group) * GM + (id % per_group) % GM;
    const int n_tile = (id % per_group) / GM;
    const int m0 = m_tile * TBM;
    const int n0 = n_tile * TBN;

    const uint16_t* Abase = (const uint16_t*)g_xh;
    const uint16_t* Bbase = (const uint16_t*)(MAIN ? g_wh : g_wrh);

    auto load_chunk = [&](int chunk, int stage) {
        const uint16_t* Ap = Abase + (size_t)m0 * IN + chunk * BK;
        const uint16_t* Bp = Bbase + (size_t)n0 * IN + chunk * BK;
        const uint32_t sA = smem_base + stage * STG;
        const uint32_t sB = sA + A_B;
#pragma unroll
        for (int it = 0; it < (TBM * 8) / NTH; it++) {
            int s = tid + it * NTH;
            int row = s >> 3, c = s & 7;
            CP_ASYNC16(sA + SWZ128((uint32_t)(row * 128 + c * 16)),
                       (const void*)(Ap + (size_t)row * IN + c * 8));
        }
#pragma unroll
        for (int it = 0; it < (TBN * 8) / NTH; it++) {
            int s = tid + it * NTH;
            int row = s >> 3, c = s & 7;
            CP_ASYNC16(sB + SWZ128((uint32_t)(row * 128 + c * 16)),
                       (const void*)(Bp + (size_t)row * IN + c * 8));
        }
    };

    // ldmatrix per-thread addressing
    const int xorv = lane & 7;
    const int a_hi = lane >> 4;
    const int b_hi = (lane >> 3) & 1;
    uint32_t a_row[MT], b_row[NT2];
#pragma unroll
    for (int mt = 0; mt < MT; mt++)
        a_row[mt] = (uint32_t)((warp_m * WM + mt * 16 + (lane & 15)) * 128);
#pragma unroll
    for (int nt2 = 0; nt2 < NT2; nt2++)
        b_row[nt2] = (uint32_t)(A_B +
                     (warp_n * WN + nt2 * 16 + ((lane & 7) | ((lane & 16) >> 1))) * 128);

    auto ldfrags = [&](uint32_t sbase, int ks, uint32_t (*af)[4], uint32_t (*bf)[4]) {
        const uint32_t ach = (uint32_t)((ks * 2 + a_hi) ^ xorv) << 4;
        const uint32_t bch = (uint32_t)((ks * 2 + b_hi) ^ xorv) << 4;
#pragma unroll
        for (int mt = 0; mt < MT; mt++)
            ldsm_x4(af[mt], sbase + a_row[mt] + ach);
#pragma unroll
        for (int nt2 = 0; nt2 < NT2; nt2++)
            ldsm_x4(bf[nt2], sbase + b_row[nt2] + bch);
    };

    float acc[MT][NT8][4] = {};

    auto mma_all = [&](uint32_t (*af)[4], uint32_t (*bf)[4]) {
#pragma unroll
        for (int mt = 0; mt < MT; mt++)
#pragma unroll
            for (int nt2 = 0; nt2 < NT2; nt2++) {
                mma16816_f16(acc[mt][nt2 * 2 + 0], af[mt], bf[nt2][0], bf[nt2][1]);
                mma16816_f16(acc[mt][nt2 * 2 + 1], af[mt], bf[nt2][2], bf[nt2][3]);
            }
    };

    uint32_t afA[MT][4], bfA[NT2][4];   // ping
    uint32_t afB[MT][4], bfB[NT2][4];   // pong

    // prologue: load NSTG-1 chunks; make chunks 0 and 1 resident; preload ks0
#pragma unroll
    for (int s = 0; s < NSTG - 1; s++) { load_chunk(s, s); CP_COMMIT(); }
    cp_wait<NSTG - 3>();
    __syncthreads();
    ldfrags(smem_base, 0, afA, bfA);

    for (int i = 0; i < NCH; i++) {
        const int nxt = i + NSTG - 1;
        if (nxt < NCH) load_chunk(nxt, nxt % NSTG);
        CP_COMMIT();

        const uint32_t sb_i = smem_base + (i % NSTG) * STG;
        const uint32_t sb_n = smem_base + ((i + 1) % NSTG) * STG;

        ldfrags(sb_i, 1, afB, bfB);
        mma_all(afA, bfA);
        ldfrags(sb_i, 2, afA, bfA);
        mma_all(afB, bfB);
        ldfrags(sb_i, 3, afB, bfB);
        mma_all(afA, bfA);
        ldfrags(sb_n, 0, afA, bfA);     // next chunk ks0 (stale-safe on last)
        mma_all(afB, bfB);

        cp_wait<NSTG - 3>();
        __syncthreads();
    }

    // ---------------- epilogue (C frag: rows qrow,+8; cols qcol,+1) ---------
    const int qrow = lane >> 2;
    const int qcol = (lane & 3) * 2;

    if (MAIN) {
        const float* b0v = p0;
        const float* u   = p1;
        // stage u[n0 .. n0+TBN) x POOLS into smem (padded stride 132 words)
        float* us = (float*)smem;
        constexpr int USTR = 132;
#pragma unroll 4
        for (int idx = tid; idx < TBN * (POOLS / 4); idx += NTH) {
            int o  = idx >> 5;           // 32 float4 per row
            int p4 = idx & 31;
            float4 v = *(const float4*)(u + (size_t)(n0 + o) * POOLS + p4 * 4);
            *(float4*)(us + o * USTR + p4 * 4) = v;
        }
        __syncthreads();

        float bo[NT8][2];
#pragma unroll
        for (int nt = 0; nt < NT8; nt++) {
            int o = n0 + warp_n * WN + nt * 8 + qcol;
            bo[nt][0] = b0v[o];
            bo[nt][1] = b0v[o + 1];
        }
#pragma unroll
        for (int mt = 0; mt < MT; mt++)
#pragma unroll
            for (int g = 0; g < 2; g++) {
                const int ntok = m0 + warp_m * WM + mt * 16 + g * 8 + qrow;
                const float d0 = g_dotv[2 * ntok], d1 = g_dotv[2 * ntok + 1];
                const int   pp0 = g_idxv[2 * ntok], pp1 = g_idxv[2 * ntok + 1];
#pragma unroll
                for (int nt = 0; nt < NT8; nt++) {
                    const int ol = warp_n * WN + nt * 8 + qcol;
                    float v0 = acc[mt][nt][g * 2 + 0] * INV_WSCALE + bo[nt][0]
                             + d0 * us[ol * USTR + pp0]
                             + d1 * us[ol * USTR + pp1];
                    float v1 = acc[mt][nt][g * 2 + 1] * INV_WSCALE + bo[nt][1]
                             + d0 * us[(ol + 1) * USTR + pp0]
                             + d1 * us[(ol + 1) * USTR + pp1];
                    *(float2*)(out + (size_t)ntok * OUT + n0 + ol) = make_float2(v0, v1);
                }
            }
    } else {
        // ---- router epilogue: logits(x1024) -> smem, top-2, exact fixup ----
        const float* x32  = p0;
        const float* wr32 = p1;
        constexpr int LSTR = 130;
        float* lg     = (float*)smem;                       // 64*130*4 = 33280
        int*   sidx   = (int*)(smem + 33280);               // 64*2 ints
        float* sv1    = (float*)(smem + 33792);             // 64 floats
        int*   scnt   = (int*)(smem + 34048);               // 64 ints
        int*   scand  = (int*)(smem + 34304);               // 64*8 ints
        float* sexact = (float*)(smem + 36352);             // 64*8 floats

#pragma unroll
        for (int mt = 0; mt < MT; mt++)
#pragma unroll
            for (int g = 0; g < 2; g++) {
                const int r = warp_m * WM + mt * 16 + g * 8 + qrow;
#pragma unroll
                for (int nt = 0; nt < NT8; nt++) {
                    const int o = warp_n * WN + nt * 8 + qcol;
                    *(float2*)(lg + r * LSTR + o) =
                        make_float2(acc[mt][nt][g * 2 + 0], acc[mt][nt][g * 2 + 1]);
                }
            }
        __syncthreads();

        // top-2 per token: 4 threads per token (t = tid>>2), shfl merge
        {
            const int t = tid >> 2, sl = tid & 3;
            float v0 = -3.402823466e38f, v1 = -3.402823466e38f;
            int i0 = 0, i1 = 0;
            for (int p = sl; p < POOLS; p += 4) {
                float v = lg[t * LSTR + p];
                if (v > v0)      { v1 = v0; i1 = i0; v0 = v; i0 = p; }
                else if (v > v1) { v1 = v;  i1 = p; }
            }
#pragma unroll
            for (int off = 2; off >= 1; off >>= 1) {
                float ov0 = __shfl_down_sync(0xffffffffu, v0, off);
                float ov1 = __shfl_down_sync(0xffffffffu, v1, off);
                int   oi0 = __shfl_down_sync(0xffffffffu, i0, off);
                int   oi1 = __shfl_down_sync(0xffffffffu, i1, off);
                if (ov0 > v0) {
                    float tv = v0; int ti = i0;
                    v0 = ov0; i0 = oi0;
                    if (tv > ov1) { v1 = tv;  i1 = ti;  }
                    else          { v1 = ov1; i1 = oi1; }
                } else if (ov0 > v1) {
                    v1 = ov0; i1 = oi0;
                }
            }
            if (sl == 0) {
                sidx[2 * t]     = i0;
                sidx[2 * t + 1] = i1;
                sv1[t]          = v1;
            }
        }
        __syncthreads();

        // candidate scan: pools within RTHRESH of the 2nd-best fp16 logit
        if (tid < TBM) {
            const int t = tid;
            const int i0 = sidx[2 * t], i1 = sidx[2 * t + 1];
            const float base = sv1[t] - RTHRESH;
            scand[t * 8 + 0] = i0;
            scand[t * 8 + 1] = i1;
            int n = 2;
            for (int p = 0; p < POOLS && n < 8; p++) {
                if (p == i0 || p == i1) continue;
                if (lg[t * LSTR + p] >= base) scand[t * 8 + n++] = p;
            }
            scnt[t] = n;
        }
        __syncthreads();

        // exact fp32 re-score of candidates for ambiguous tokens (warp/dot)
        for (int t = wid * 8; t < wid * 8 + 8; t++) {
            const int n = scnt[t];
            if (n <= 2) continue;
            const float4* xr = (const float4*)(x32 + (size_t)(m0 + t) * IN);
            for (int c = 0; c < n; c++) {
                const int pool = scand[t * 8 + c];
                const float4* wp = (const float4*)(wr32 + (size_t)pool * IN);
                float a = 0.f;
                for (int i = lane; i < IN / 4; i += 32) {
                    float4 xv = xr[i], wv = wp[i];
                    a += xv.x * wv.x + xv.y * wv.y + xv.z * wv.z + xv.w * wv.w;
                }
#pragma unroll
                for (int off = 16; off; off >>= 1)
                    a += __shfl_down_sync(0xffffffffu, a, off);
                if (lane == 0) sexact[t * 8 + c] = a;
            }
        }
        __syncthreads();

        // re-select among exact candidate values for ambiguous tokens
        if (tid < TBM && scnt[tid] > 2) {
            const int t = tid, n = scnt[t];
            float v0 = -3.402823466e38f, v1 = -3.402823466e38f;
            int i0 = 0, i1 = 0;
            for (int c = 0; c < n; c++) {
                float v = sexact[t * 8 + c];
                int   p = scand[t * 8 + c];
                if (v > v0)      { v1 = v0; i1 = i0; v0 = v; i0 = p; }
                else if (v > v1) { v1 = v;  i1 = p; }
            }
            sidx[2 * t]     = i0;
            sidx[2 * t + 1] = i1;
        }
        __syncthreads();

        // publish indices + fused per-token dual dot(xh, svh16[p0], svh16[p1])
        if (tid < TBM) {
            const int n = m0 + tid;
            g_idxv[2 * n]     = sidx[2 * tid];
            g_idxv[2 * n + 1] = sidx[2 * tid + 1];
        }
        for (int t = wid * 8; t < wid * 8 + 8; t++) {
            const int pp0 = sidx[2 * t], pp1 = sidx[2 * t + 1];
            const __half2* xr = (const __half2*)(g_xh   + (size_t)(m0 + t) * IN);
            const __half2* s0 = (const __half2*)(g_svhh + (size_t)pp0 * IN);
            const __half2* s1 = (const __half2*)(g_svhh + (size_t)pp1 * IN);
            float a0 = 0.f, a1 = 0.f;
#pragma unroll 4
            for (int i = lane; i < IN / 2; i += 32) {
                float2 xv = __half22float2(xr[i]);
                float2 v0 = __half22float2(s0[i]);
                float2 v1 = __half22float2(s1[i]);
                a0 += xv.x * v0.x + xv.y * v0.y;
                a1 += xv.x * v1.x + xv.y * v1.y;
            }
#pragma unroll
            for (int off = 16; off; off >>= 1) {
                a0 += __shfl_down_sync(0xffffffffu, a0, off);
                a1 += __shfl_down_sync(0xffffffffu, a1, off);
            }
            if (lane == 0) {
                g_dotv[2 * (m0 + t)]     = a0;
                g_dotv[2 * (m0 + t) + 1] = a1;
            }
        }
    }
}

// ---------------------------------------------------------------------------
// Launch — split_xw runs alone (full DRAM speed); split_w on stream2
// overlaps the compute-bound router; main GEMM joins both.
// ---------------------------------------------------------------------------
extern "C" void kernel_launch(void* const* d_in, const int* in_sizes, int n_in,
                              void* d_out, int out_size) {
    const float* x   = (const float*)d_in[0];
    const float* w0  = (const float*)d_in[1];
    const float* b0  = (const float*)d_in[2];
    const float* wr  = (const float*)d_in[3];
    const float* u   = (const float*)d_in[4];
    const float* svh = (const float*)d_in[5];
    float* out = (float*)d_out;

    // main: BM=128, BN=256, 8 warps, 4 stages -> 192 KB smem
    constexpr int SMEM_MAIN = 4 * (128 + 256) * 128;        // 196,608 B
    // router: BM=64, BN=128, 8 warps, 4 stages -> 96 KB smem
    constexpr int SMEM_RTR  = 4 * (64 + 128) * 128;         //  98,304 B

    cudaFuncSetAttribute((const void*)gemm_kernel<128, 256, 4, true>,
                         cudaFuncAttributeMaxDynamicSharedMemorySize, SMEM_MAIN);
    cudaFuncSetAttribute((const void*)gemm_kernel<64, 128, 4, false>,
                         cudaFuncAttributeMaxDynamicSharedMemorySize, SMEM_RTR);

    // Fork resources (host-side objects only; no device memory).
    cudaStream_t s2;
    cudaEvent_t evFork, evJoin;
    bool forked = (cudaStreamCreateWithFlags(&s2, cudaStreamNonBlocking) == cudaSuccess)
               && (cudaEventCreateWithFlags(&evFork, cudaEventDisableTiming) == cudaSuccess)
               && (cudaEventCreateWithFlags(&evJoin, cudaEventDisableTiming) == cudaSuccess);

    if (forked) {
        // 0) x/wr/svh fp16 conversions — runs alone at full DRAM bandwidth
        split_xw_kernel<<<XBLK + RBLK + SBLK, 256>>>(
            (const float4*)x, (const float4*)wr, (const float4*)svh);

        // fork AFTER split_xw: split_w (DRAM-bound) overlaps the router
        // (compute-bound) instead of competing with split_xw for DRAM.
        cudaEventRecord(evFork, 0);
        cudaStreamWaitEvent(s2, evFork, 0);
        split_w_kernel<<<512, 256, 0, s2>>>((const float4*)w0);
        cudaEventRecord(evJoin, s2);

        // 1) router logits + top-2 + exact fixup + fused dual dots
        gemm_kernel<64, 128, 4, false>
            <<<NTOK / 64, 256, SMEM_RTR>>>(x, wr, nullptr);

        // join, then main GEMM
        cudaStreamWaitEvent(0, evJoin, 0);
        gemm_kernel<128, 256, 4, true>
            <<<(NTOK / 128) * (OUT / 256), 256, SMEM_MAIN>>>(b0, u, out);
    } else {
        // serial fallback
        split_xw_kernel<<<XBLK + RBLK + SBLK, 256>>>(
            (const float4*)x, (const float4*)wr, (const float4*)svh);
        split_w_kernel<<<512, 256>>>((const float4*)w0);
        gemm_kernel<64, 128, 4, false>
            <<<NTOK / 64, 256, SMEM_RTR>>>(x, wr, nullptr);
        gemm_kernel<128, 256, 4, true>
            <<<(NTOK / 128) * (OUT / 256), 256, SMEM_MAIN>>>(b0, u, out);
    }
}

// round 15
// speedup vs baseline: 1.0234x; 1.0234x over previous
#include <cuda_runtime.h>
#include <cuda_bf16.h>
#include <cuda_fp16.h>
#include <cstdint>

#define DINLINE __device__ __forceinline__

// ---------------------------------------------------------------------------
// Problem constants
// ---------------------------------------------------------------------------
constexpr int NTOK  = 8192;   // B*S tokens
constexpr int IN    = 4096;
constexpr int OUT   = 4096;
constexpr int POOLS = 128;

constexpr int BK = 64;        // 16-bit elems per k-chunk -> 128B rows

constexpr float WSCALE     = 1024.0f;   // weight prescale (w0 and wr)
constexpr float INV_WSCALE = 1.0f / 1024.0f;

// Router ambiguity threshold in scaled-logit units (logits carry x1024 from
// wr prescale; per-logit fp16 error sigma ~= 0.9 in these units).
constexpr float RTHRESH = 52.0f;

// ---------------------------------------------------------------------------
// Device scratch (static __device__ globals only — no runtime allocation)
// ---------------------------------------------------------------------------
__device__ __align__(1024) __half g_xh  [(size_t)NTOK * IN];    // fp16(x)
__device__ __align__(1024) __half g_wh  [(size_t)OUT * IN];     // fp16(1024*w0)
__device__ __align__(1024) __half g_wrh [(size_t)POOLS * IN];   // fp16(1024*wr)
__device__ __align__(1024) __half g_svhh[(size_t)POOLS * IN];   // fp16(svh)
__device__ float g_dotv[(size_t)NTOK * 2];
__device__ int   g_idxv[(size_t)NTOK * 2];

// ---------------------------------------------------------------------------
// Portable PTX helpers (plain sm_103 target — no tcgen05)
// ---------------------------------------------------------------------------
DINLINE uint32_t smem_u32(const void* p) {
    uint32_t a;
    asm("{ .reg .u64 t; cvta.to.shared.u64 t, %1; cvt.u32.u64 %0, t; }" : "=r"(a) : "l"(p));
    return a;
}

// 128B-row swizzle: 16B-chunk index (bits 4..6) ^= low 3 bits of row (bits 7..9)
#define SWZ128(o) ((o) ^ (((o) >> 3) & 0x70))

#define CP_ASYNC16(saddr, gptr) \
    asm volatile("cp.async.cg.shared.global [%0], [%1], 16;" :: "r"(saddr), "l"(gptr))
#define CP_COMMIT() asm volatile("cp.async.commit_group;" ::: "memory")

template <int N>
DINLINE void cp_wait() { asm volatile("cp.async.wait_group %0;" :: "n"(N) : "memory"); }

DINLINE void ldsm_x4(uint32_t* r, uint32_t addr) {
    asm volatile("ldmatrix.sync.aligned.m8n8.x4.shared.b16 {%0,%1,%2,%3}, [%4];"
                 : "=r"(r[0]), "=r"(r[1]), "=r"(r[2]), "=r"(r[3]) : "r"(addr));
}

DINLINE void mma16816_f16(float* d, const uint32_t* a, uint32_t b0, uint32_t b1) {
    asm volatile(
        "mma.sync.aligned.m16n8k16.row.col.f32.f16.f16.f32 "
        "{%0,%1,%2,%3}, {%4,%5,%6,%7}, {%8,%9}, {%0,%1,%2,%3};"
        : "+f"(d[0]), "+f"(d[1]), "+f"(d[2]), "+f"(d[3])
        : "r"(a[0]), "r"(a[1]), "r"(a[2]), "r"(a[3]), "r"(b0), "r"(b1));
}

DINLINE uint32_t pack_h2(float a, float b) {
    __half2 t = __floats2half2_rn(a, b);
    return *(uint32_t*)&t;
}

// ---------------------------------------------------------------------------
// Kernel 0a: x -> fp16 ; wr -> fp16(1024*wr) ; svh -> fp16.
// ---------------------------------------------------------------------------
constexpr int XBLK = 1024, RBLK = 8, SBLK = 8;

__global__ void __launch_bounds__(256)
split_xw_kernel(const float4* __restrict__ x4, const float4* __restrict__ wr4,
                const float4* __restrict__ svh4) {
    const int bid = blockIdx.x;
    if (bid < XBLK) {
        const int n4 = NTOK * IN / 4;
        const int stride = XBLK * 256;
        uint2* f2 = (uint2*)g_xh;
        for (int i = bid * 256 + threadIdx.x; i < n4; i += stride) {
            float4 v = x4[i];
            f2[i] = make_uint2(pack_h2(v.x, v.y), pack_h2(v.z, v.w));
        }
    } else if (bid < XBLK + RBLK) {
        const int n4 = POOLS * IN / 4;
        const int stride = RBLK * 256;
        uint2* f2 = (uint2*)g_wrh;
        for (int i = (bid - XBLK) * 256 + threadIdx.x; i < n4; i += stride) {
            float4 v = wr4[i];
            f2[i] = make_uint2(pack_h2(v.x * WSCALE, v.y * WSCALE),
                               pack_h2(v.z * WSCALE, v.w * WSCALE));
        }
    } else {
        const int n4 = POOLS * IN / 4;
        const int stride = SBLK * 256;
        uint2* f2 = (uint2*)g_svhh;
        for (int i = (bid - XBLK - RBLK) * 256 + threadIdx.x; i < n4; i += stride) {
            float4 v = svh4[i];
            f2[i] = make_uint2(pack_h2(v.x, v.y), pack_h2(v.z, v.w));
        }
    }
}

// Kernel 0b: w0 -> fp16(WSCALE*w0). Stream2, forked BEFORE split_xw (R13
// ordering: its DRAM traffic hides under split_xw + router without touching
// the router's latency-sensitive critical path).
__global__ void __launch_bounds__(256)
split_w_kernel(const float4* __restrict__ w4) {
    const int n4 = OUT * IN / 4;
    const int stride = gridDim.x * 256;
    uint2* h2 = (uint2*)g_wh;
    for (int i = blockIdx.x * 256 + threadIdx.x; i < n4; i += stride) {
        float4 v = w4[i];
        h2[i] = make_uint2(pack_h2(v.x * WSCALE, v.y * WSCALE),
                           pack_h2(v.z * WSCALE, v.w * WSCALE));
    }
}

// ---------------------------------------------------------------------------
// GEMM: out = x @ W^T, single-segment fp16, K = 4096 (64 chunks).
//   MAIN=false: router logits (BM=64, BN=128). Epilogue: fp16 top-2 with
//               margin test; ambiguous tokens re-scored with exact fp32 dots;
//               then fused per-token dual dot(xh, svh16[sel0/1]).
//   MAIN=true : main GEMM (BM=128, BN=256); epilogue: *1/1024 + b0 +
//               rank-one expert combine.
// 8 warps = 2(m) x 4(n); cp.async 4-stage pipeline, two chunks resident;
// fragment double-buffering with cross-chunk ldsm lookahead.
//   p0 = (MAIN ? b0 : x_fp32), p1 = (MAIN ? u : wr_fp32)
// ---------------------------------------------------------------------------
template <int TBM, int TBN, int NSTG, bool MAIN>
__global__ void __launch_bounds__(256, 1)
gemm_kernel(const float* __restrict__ p0, const float* __restrict__ p1,
            float* __restrict__ out) {
    static_assert(NSTG >= 3, "need two chunks resident");
    constexpr int NTH = 256;
    constexpr int WMN = 2, WNN = 4;
    constexpr int WM  = TBM / WMN;
    constexpr int WN  = TBN / WNN;
    constexpr int MT  = WM / 16;
    constexpr int NT2 = WN / 16;
    constexpr int NT8 = WN / 8;
    constexpr int A_B = TBM * 128;
    constexpr int B_B = TBN * 128;
    constexpr int STG = A_B + B_B;
    constexpr int NCH = IN / BK;          // 64

    extern __shared__ __align__(1024) char smem[];
    const uint32_t smem_base = smem_u32(smem);

    const int tid    = threadIdx.x;
    const int wid    = tid >> 5;
    const int lane   = tid & 31;
    const int warp_m = wid & 1;
    const int warp_n = wid >> 1;

    // group-swizzled CTA rasterization (L2 reuse)
    constexpr int GM = 16;
    const int num_n = MAIN ? (OUT / TBN) : 1;
    const int per_group = GM * num_n;
    const int id = blockIdx.x;
    const int m_tile = (id / per_group) * GM + (id % per_group) % GM;
    const int n_tile = (id % per_group) / GM;
    const int m0 = m_tile * TBM;
    const int n0 = n_tile * TBN;

    const uint16_t* Abase = (const uint16_t*)g_xh;
    const uint16_t* Bbase = (const uint16_t*)(MAIN ? g_wh : g_wrh);

    auto load_chunk = [&](int chunk, int stage) {
        const uint16_t* Ap = Abase + (size_t)m0 * IN + chunk * BK;
        const uint16_t* Bp = Bbase + (size_t)n0 * IN + chunk * BK;
        const uint32_t sA = smem_base + stage * STG;
        const uint32_t sB = sA + A_B;
#pragma unroll
        for (int it = 0; it < (TBM * 8) / NTH; it++) {
            int s = tid + it * NTH;
            int row = s >> 3, c = s & 7;
            CP_ASYNC16(sA + SWZ128((uint32_t)(row * 128 + c * 16)),
                       (const void*)(Ap + (size_t)row * IN + c * 8));
        }
#pragma unroll
        for (int it = 0; it < (TBN * 8) / NTH; it++) {
            int s = tid + it * NTH;
            int row = s >> 3, c = s & 7;
            CP_ASYNC16(sB + SWZ128((uint32_t)(row * 128 + c * 16)),
                       (const void*)(Bp + (size_t)row * IN + c * 8));
        }
    };

    // ldmatrix per-thread addressing
    const int xorv = lane & 7;
    const int a_hi = lane >> 4;
    const int b_hi = (lane >> 3) & 1;
    uint32_t a_row[MT], b_row[NT2];
#pragma unroll
    for (int mt = 0; mt < MT; mt++)
        a_row[mt] = (uint32_t)((warp_m * WM + mt * 16 + (lane & 15)) * 128);
#pragma unroll
    for (int nt2 = 0; nt2 < NT2; nt2++)
        b_row[nt2] = (uint32_t)(A_B +
                     (warp_n * WN + nt2 * 16 + ((lane & 7) | ((lane & 16) >> 1))) * 128);

    auto ldfrags = [&](uint32_t sbase, int ks, uint32_t (*af)[4], uint32_t (*bf)[4]) {
        const uint32_t ach = (uint32_t)((ks * 2 + a_hi) ^ xorv) << 4;
        const uint32_t bch = (uint32_t)((ks * 2 + b_hi) ^ xorv) << 4;
#pragma unroll
        for (int mt = 0; mt < MT; mt++)
            ldsm_x4(af[mt], sbase + a_row[mt] + ach);
#pragma unroll
        for (int nt2 = 0; nt2 < NT2; nt2++)
            ldsm_x4(bf[nt2], sbase + b_row[nt2] + bch);
    };

    float acc[MT][NT8][4] = {};

    auto mma_all = [&](uint32_t (*af)[4], uint32_t (*bf)[4]) {
#pragma unroll
        for (int mt = 0; mt < MT; mt++)
#pragma unroll
            for (int nt2 = 0; nt2 < NT2; nt2++) {
                mma16816_f16(acc[mt][nt2 * 2 + 0], af[mt], bf[nt2][0], bf[nt2][1]);
                mma16816_f16(acc[mt][nt2 * 2 + 1], af[mt], bf[nt2][2], bf[nt2][3]);
            }
    };

    uint32_t afA[MT][4], bfA[NT2][4];   // ping
    uint32_t afB[MT][4], bfB[NT2][4];   // pong

    // prologue: load NSTG-1 chunks; make chunks 0 and 1 resident; preload ks0
#pragma unroll
    for (int s = 0; s < NSTG - 1; s++) { load_chunk(s, s); CP_COMMIT(); }
    cp_wait<NSTG - 3>();
    __syncthreads();
    ldfrags(smem_base, 0, afA, bfA);

    for (int i = 0; i < NCH; i++) {
        const int nxt = i + NSTG - 1;
        if (nxt < NCH) load_chunk(nxt, nxt % NSTG);
        CP_COMMIT();

        const uint32_t sb_i = smem_base + (i % NSTG) * STG;
        const uint32_t sb_n = smem_base + ((i + 1) % NSTG) * STG;

        ldfrags(sb_i, 1, afB, bfB);
        mma_all(afA, bfA);
        ldfrags(sb_i, 2, afA, bfA);
        mma_all(afB, bfB);
        ldfrags(sb_i, 3, afB, bfB);
        mma_all(afA, bfA);
        ldfrags(sb_n, 0, afA, bfA);     // next chunk ks0 (stale-safe on last)
        mma_all(afB, bfB);

        cp_wait<NSTG - 3>();
        __syncthreads();
    }

    // ---------------- epilogue (C frag: rows qrow,+8; cols qcol,+1) ---------
    const int qrow = lane >> 2;
    const int qcol = (lane & 3) * 2;

    if (MAIN) {
        const float* b0v = p0;
        const float* u   = p1;
        // stage u[n0 .. n0+TBN) x POOLS into smem (padded stride 132 words)
        float* us = (float*)smem;
        constexpr int USTR = 132;
#pragma unroll 4
        for (int idx = tid; idx < TBN * (POOLS / 4); idx += NTH) {
            int o  = idx >> 5;           // 32 float4 per row
            int p4 = idx & 31;
            float4 v = *(const float4*)(u + (size_t)(n0 + o) * POOLS + p4 * 4);
            *(float4*)(us + o * USTR + p4 * 4) = v;
        }
        __syncthreads();

        float bo[NT8][2];
#pragma unroll
        for (int nt = 0; nt < NT8; nt++) {
            int o = n0 + warp_n * WN + nt * 8 + qcol;
            bo[nt][0] = b0v[o];
            bo[nt][1] = b0v[o + 1];
        }
#pragma unroll
        for (int mt = 0; mt < MT; mt++)
#pragma unroll
            for (int g = 0; g < 2; g++) {
                const int ntok = m0 + warp_m * WM + mt * 16 + g * 8 + qrow;
                const float d0 = g_dotv[2 * ntok], d1 = g_dotv[2 * ntok + 1];
                const int   pp0 = g_idxv[2 * ntok], pp1 = g_idxv[2 * ntok + 1];
#pragma unroll
                for (int nt = 0; nt < NT8; nt++) {
                    const int ol = warp_n * WN + nt * 8 + qcol;
                    float v0 = acc[mt][nt][g * 2 + 0] * INV_WSCALE + bo[nt][0]
                             + d0 * us[ol * USTR + pp0]
                             + d1 * us[ol * USTR + pp1];
                    float v1 = acc[mt][nt][g * 2 + 1] * INV_WSCALE + bo[nt][1]
                             + d0 * us[(ol + 1) * USTR + pp0]
                             + d1 * us[(ol + 1) * USTR + pp1];
                    *(float2*)(out + (size_t)ntok * OUT + n0 + ol) = make_float2(v0, v1);
                }
            }
    } else {
        // ---- router epilogue: logits(x1024) -> smem, top-2, exact fixup ----
        const float* x32  = p0;
        const float* wr32 = p1;
        constexpr int LSTR = 130;
        float* lg     = (float*)smem;                       // 64*130*4 = 33280
        int*   sidx   = (int*)(smem + 33280);               // 64*2 ints
        float* sv1    = (float*)(smem + 33792);             // 64 floats
        int*   scnt   = (int*)(smem + 34048);               // 64 ints
        int*   scand  = (int*)(smem + 34304);               // 64*8 ints
        float* sexact = (float*)(smem + 36352);             // 64*8 floats

#pragma unroll
        for (int mt = 0; mt < MT; mt++)
#pragma unroll
            for (int g = 0; g < 2; g++) {
                const int r = warp_m * WM + mt * 16 + g * 8 + qrow;
#pragma unroll
                for (int nt = 0; nt < NT8; nt++) {
                    const int o = warp_n * WN + nt * 8 + qcol;
                    *(float2*)(lg + r * LSTR + o) =
                        make_float2(acc[mt][nt][g * 2 + 0], acc[mt][nt][g * 2 + 1]);
                }
            }
        __syncthreads();

        // top-2 per token: 4 threads per token (t = tid>>2), shfl merge
        {
            const int t = tid >> 2, sl = tid & 3;
            float v0 = -3.402823466e38f, v1 = -3.402823466e38f;
            int i0 = 0, i1 = 0;
            for (int p = sl; p < POOLS; p += 4) {
                float v = lg[t * LSTR + p];
                if (v > v0)      { v1 = v0; i1 = i0; v0 = v; i0 = p; }
                else if (v > v1) { v1 = v;  i1 = p; }
            }
#pragma unroll
            for (int off = 2; off >= 1; off >>= 1) {
                float ov0 = __shfl_down_sync(0xffffffffu, v0, off);
                float ov1 = __shfl_down_sync(0xffffffffu, v1, off);
                int   oi0 = __shfl_down_sync(0xffffffffu, i0, off);
                int   oi1 = __shfl_down_sync(0xffffffffu, i1, off);
                if (ov0 > v0) {
                    float tv = v0; int ti = i0;
                    v0 = ov0; i0 = oi0;
                    if (tv > ov1) { v1 = tv;  i1 = ti;  }
                    else          { v1 = ov1; i1 = oi1; }
                } else if (ov0 > v1) {
                    v1 = ov0; i1 = oi0;
                }
            }
            if (sl == 0) {
                sidx[2 * t]     = i0;
                sidx[2 * t + 1] = i1;
                sv1[t]          = v1;
            }
        }
        __syncthreads();

        // candidate scan: pools within RTHRESH of the 2nd-best fp16 logit
        if (tid < TBM) {
            const int t = tid;
            const int i0 = sidx[2 * t], i1 = sidx[2 * t + 1];
            const float base = sv1[t] - RTHRESH;
            scand[t * 8 + 0] = i0;
            scand[t * 8 + 1] = i1;
            int n = 2;
            for (int p = 0; p < POOLS && n < 8; p++) {
                if (p == i0 || p == i1) continue;
                if (lg[t * LSTR + p] >= base) scand[t * 8 + n++] = p;
            }
            scnt[t] = n;
        }
        __syncthreads();

        // exact fp32 re-score of candidates for ambiguous tokens (warp/dot)
        for (int t = wid * 8; t < wid * 8 + 8; t++) {
            const int n = scnt[t];
            if (n <= 2) continue;
            const float4* xr = (const float4*)(x32 + (size_t)(m0 + t) * IN);
            for (int c = 0; c < n; c++) {
                const int pool = scand[t * 8 + c];
                const float4* wp = (const float4*)(wr32 + (size_t)pool * IN);
                float a = 0.f;
                for (int i = lane; i < IN / 4; i += 32) {
                    float4 xv = xr[i], wv = wp[i];
                    a += xv.x * wv.x + xv.y * wv.y + xv.z * wv.z + xv.w * wv.w;
                }
#pragma unroll
                for (int off = 16; off; off >>= 1)
                    a += __shfl_down_sync(0xffffffffu, a, off);
                if (lane == 0) sexact[t * 8 + c] = a;
            }
        }
        __syncthreads();

        // re-select among exact candidate values for ambiguous tokens
        if (tid < TBM && scnt[tid] > 2) {
            const int t = tid, n = scnt[t];
            float v0 = -3.402823466e38f, v1 = -3.402823466e38f;
            int i0 = 0, i1 = 0;
            for (int c = 0; c < n; c++) {
                float v = sexact[t * 8 + c];
                int   p = scand[t * 8 + c];
                if (v > v0)      { v1 = v0; i1 = i0; v0 = v; i0 = p; }
                else if (v > v1) { v1 = v;  i1 = p; }
            }
            sidx[2 * t]     = i0;
            sidx[2 * t + 1] = i1;
        }
        __syncthreads();

        // publish indices + fused per-token dual dot(xh, svh16[p0], svh16[p1])
        if (tid < TBM) {
            const int n = m0 + tid;
            g_idxv[2 * n]     = sidx[2 * tid];
            g_idxv[2 * n + 1] = sidx[2 * tid + 1];
        }
        for (int t = wid * 8; t < wid * 8 + 8; t++) {
            const int pp0 = sidx[2 * t], pp1 = sidx[2 * t + 1];
            const __half2* xr = (const __half2*)(g_xh   + (size_t)(m0 + t) * IN);
            const __half2* s0 = (const __half2*)(g_svhh + (size_t)pp0 * IN);
            const __half2* s1 = (const __half2*)(g_svhh + (size_t)pp1 * IN);
            float a0 = 0.f, a1 = 0.f;
#pragma unroll 4
            for (int i = lane; i < IN / 2; i += 32) {
                float2 xv = __half22float2(xr[i]);
                float2 v0 = __half22float2(s0[i]);
                float2 v1 = __half22float2(s1[i]);
                a0 += xv.x * v0.x + xv.y * v0.y;
                a1 += xv.x * v1.x + xv.y * v1.y;
            }
#pragma unroll
            for (int off = 16; off; off >>= 1) {
                a0 += __shfl_down_sync(0xffffffffu, a0, off);
                a1 += __shfl_down_sync(0xffffffffu, a1, off);
            }
            if (lane == 0) {
                g_dotv[2 * (m0 + t)]     = a0;
                g_dotv[2 * (m0 + t) + 1] = a1;
            }
        }
    }
}

// ---------------------------------------------------------------------------
// Launch — R13 fork ordering: split_w (stream2) overlaps split_xw + router;
// main GEMM joins both branches.
// ---------------------------------------------------------------------------
extern "C" void kernel_launch(void* const* d_in, const int* in_sizes, int n_in,
                              void* d_out, int out_size) {
    const float* x   = (const float*)d_in[0];
    const float* w0  = (const float*)d_in[1];
    const float* b0  = (const float*)d_in[2];
    const float* wr  = (const float*)d_in[3];
    const float* u   = (const float*)d_in[4];
    const float* svh = (const float*)d_in[5];
    float* out = (float*)d_out;

    // main: BM=128, BN=256, 8 warps, 4 stages -> 192 KB smem
    constexpr int SMEM_MAIN = 4 * (128 + 256) * 128;        // 196,608 B
    // router: BM=64, BN=128, 8 warps, 4 stages -> 96 KB smem
    constexpr int SMEM_RTR  = 4 * (64 + 128) * 128;         //  98,304 B

    cudaFuncSetAttribute((const void*)gemm_kernel<128, 256, 4, true>,
                         cudaFuncAttributeMaxDynamicSharedMemorySize, SMEM_MAIN);
    cudaFuncSetAttribute((const void*)gemm_kernel<64, 128, 4, false>,
                         cudaFuncAttributeMaxDynamicSharedMemorySize, SMEM_RTR);

    // Fork resources (host-side objects only; no device memory).
    cudaStream_t s2;
    cudaEvent_t evFork, evJoin;
    bool forked = (cudaStreamCreateWithFlags(&s2, cudaStreamNonBlocking) == cudaSuccess)
               && (cudaEventCreateWithFlags(&evFork, cudaEventDisableTiming) == cudaSuccess)
               && (cudaEventCreateWithFlags(&evJoin, cudaEventDisableTiming) == cudaSuccess);

    if (forked) {
        // fork FIRST (R13 ordering): split_w hides under split_xw + router
        cudaEventRecord(evFork, 0);
        cudaStreamWaitEvent(s2, evFork, 0);
        split_w_kernel<<<512, 256, 0, s2>>>((const float4*)w0);
        cudaEventRecord(evJoin, s2);

        // main-stream chain: x/wr/svh fp16 conversions -> router
        split_xw_kernel<<<XBLK + RBLK + SBLK, 256>>>(
            (const float4*)x, (const float4*)wr, (const float4*)svh);
        gemm_kernel<64, 128, 4, false>
            <<<NTOK / 64, 256, SMEM_RTR>>>(x, wr, nullptr);

        // join, then main GEMM
        cudaStreamWaitEvent(0, evJoin, 0);
        gemm_kernel<128, 256, 4, true>
            <<<(NTOK / 128) * (OUT / 256), 256, SMEM_MAIN>>>(b0, u, out);
    } else {
        // serial fallback
        split_w_kernel<<<512, 256>>>((const float4*)w0);
        split_xw_kernel<<<XBLK + RBLK + SBLK, 256>>>(
            (const float4*)x, (const float4*)wr, (const float4*)svh);
        gemm_kernel<64, 128, 4, false>
            <<<NTOK / 64, 256, SMEM_RTR>>>(x, wr, nullptr);
        gemm_kernel<128, 256, 4, true>
            <<<(NTOK / 128) * (OUT / 256), 256, SMEM_MAIN>>>(b0, u, out);
    }
}

// round 16
// speedup vs baseline: 1.0560x; 1.0318x over previous
#include <cuda_runtime.h>
#include <cuda_bf16.h>
#include <cuda_fp16.h>
#include <cstdint>

#define DINLINE __device__ __forceinline__

// ---------------------------------------------------------------------------
// Problem constants
// ---------------------------------------------------------------------------
constexpr int NTOK  = 8192;   // B*S tokens
constexpr int IN    = 4096;
constexpr int OUT   = 4096;
constexpr int POOLS = 128;

constexpr int BK = 64;        // 16-bit elems per k-chunk -> 128B rows

constexpr float WSCALE     = 1024.0f;   // weight prescale (w0 and wr)
constexpr float INV_WSCALE = 1.0f / 1024.0f;

// Router ambiguity threshold in scaled-logit units (fp16 logit sigma ~0.9).
constexpr float RTHRESH = 52.0f;

constexpr int RTR_CTAS = NTOK / 64;     // 128 router token-blocks

// ---------------------------------------------------------------------------
// Device scratch (static __device__ globals only — no runtime allocation)
// ---------------------------------------------------------------------------
__device__ __align__(1024) __half g_xh [(size_t)NTOK * IN];    // fp16(x)
__device__ __align__(1024) __half g_wh [(size_t)OUT * IN];     // fp16(1024*w0)
__device__ __align__(1024) __half g_wrh[(size_t)POOLS * IN];   // fp16(1024*wr)
__device__ float g_dotv[(size_t)NTOK * 2];
__device__ int   g_idxv[(size_t)NTOK * 2];
__device__ int   g_rtr_cnt;             // router-phase completion counter

// ---------------------------------------------------------------------------
// Portable PTX helpers (plain sm_103 target — no tcgen05)
// ---------------------------------------------------------------------------
DINLINE uint32_t smem_u32(const void* p) {
    uint32_t a;
    asm("{ .reg .u64 t; cvta.to.shared.u64 t, %1; cvt.u32.u64 %0, t; }" : "=r"(a) : "l"(p));
    return a;
}

#define SWZ128(o) ((o) ^ (((o) >> 3) & 0x70))

#define CP_ASYNC16(saddr, gptr) \
    asm volatile("cp.async.cg.shared.global [%0], [%1], 16;" :: "r"(saddr), "l"(gptr))
#define CP_COMMIT() asm volatile("cp.async.commit_group;" ::: "memory")

template <int N>
DINLINE void cp_wait() { asm volatile("cp.async.wait_group %0;" :: "n"(N) : "memory"); }

DINLINE void ldsm_x4(uint32_t* r, uint32_t addr) {
    asm volatile("ldmatrix.sync.aligned.m8n8.x4.shared.b16 {%0,%1,%2,%3}, [%4];"
                 : "=r"(r[0]), "=r"(r[1]), "=r"(r[2]), "=r"(r[3]) : "r"(addr));
}

DINLINE void mma16816_f16(float* d, const uint32_t* a, uint32_t b0, uint32_t b1) {
    asm volatile(
        "mma.sync.aligned.m16n8k16.row.col.f32.f16.f16.f32 "
        "{%0,%1,%2,%3}, {%4,%5,%6,%7}, {%8,%9}, {%0,%1,%2,%3};"
        : "+f"(d[0]), "+f"(d[1]), "+f"(d[2]), "+f"(d[3])
        : "r"(a[0]), "r"(a[1]), "r"(a[2]), "r"(a[3]), "r"(b0), "r"(b1));
}

DINLINE uint32_t pack_h2(float a, float b) {
    __half2 t = __floats2half2_rn(a, b);
    return *(uint32_t*)&t;
}

// ---------------------------------------------------------------------------
// Kernel 0a: x -> fp16 ; wr -> fp16(1024*wr). Also resets g_rtr_cnt.
// ---------------------------------------------------------------------------
constexpr int XBLK = 1024, RBLK = 8;

__global__ void __launch_bounds__(256)
split_xw_kernel(const float4* __restrict__ x4, const float4* __restrict__ wr4) {
    const int bid = blockIdx.x;
    if (bid == 0 && threadIdx.x == 0) g_rtr_cnt = 0;   // reset per launch
    if (bid < XBLK) {
        const int n4 = NTOK * IN / 4;
        const int stride = XBLK * 256;
        uint2* f2 = (uint2*)g_xh;
        for (int i = bid * 256 + threadIdx.x; i < n4; i += stride) {
            float4 v = x4[i];
            f2[i] = make_uint2(pack_h2(v.x, v.y), pack_h2(v.z, v.w));
        }
    } else {
        const int n4 = POOLS * IN / 4;
        const int stride = RBLK * 256;
        uint2* f2 = (uint2*)g_wrh;
        for (int i = (bid - XBLK) * 256 + threadIdx.x; i < n4; i += stride) {
            float4 v = wr4[i];
            f2[i] = make_uint2(pack_h2(v.x * WSCALE, v.y * WSCALE),
                               pack_h2(v.z * WSCALE, v.w * WSCALE));
        }
    }
}

// Kernel 0b: w0 -> fp16(WSCALE*w0). Stream2, forked before split_xw.
__global__ void __launch_bounds__(256)
split_w_kernel(const float4* __restrict__ w4) {
    const int n4 = OUT * IN / 4;
    const int stride = gridDim.x * 256;
    uint2* h2 = (uint2*)g_wh;
    for (int i = blockIdx.x * 256 + threadIdx.x; i < n4; i += stride) {
        float4 v = w4[i];
        h2[i] = make_uint2(pack_h2(v.x * WSCALE, v.y * WSCALE),
                           pack_h2(v.z * WSCALE, v.w * WSCALE));
    }
}

// ---------------------------------------------------------------------------
// Router phase (device function): logits = fp16 x @ fp16(1024*wr)^T for 64
// tokens, top-2 with margin test, exact fp32 fixup, fp32-svh dots.
// Runs inside the fused kernel on CTAs bid < 128. Writes g_dotv/g_idxv.
// ---------------------------------------------------------------------------
__device__ void router_phase(char* smem, uint32_t smem_base, int bid,
                             const float* __restrict__ x32,
                             const float* __restrict__ wr32,
                             const float* __restrict__ svh) {
    constexpr int TBM = 64, TBN = 128, NSTG = 4, NTH = 256;
    constexpr int WM = 32, WN = 32, MT = 2, NT2 = 2, NT8 = 4;
    constexpr int A_B = TBM * 128, B_B = TBN * 128, STG = A_B + B_B;
    constexpr int NCH = IN / BK;

    const int tid    = threadIdx.x;
    const int wid    = tid >> 5;
    const int lane   = tid & 31;
    const int warp_m = wid & 1;
    const int warp_n = wid >> 1;
    const int m0     = bid * TBM;

    const uint16_t* Abase = (const uint16_t*)g_xh;
    const uint16_t* Bbase = (const uint16_t*)g_wrh;

    auto load_chunk = [&](int chunk, int stage) {
        const uint16_t* Ap = Abase + (size_t)m0 * IN + chunk * BK;
        const uint16_t* Bp = Bbase + chunk * BK;
        const uint32_t sA = smem_base + stage * STG;
        const uint32_t sB = sA + A_B;
#pragma unroll
        for (int it = 0; it < (TBM * 8) / NTH; it++) {
            int s = tid + it * NTH;
            int row = s >> 3, c = s & 7;
            CP_ASYNC16(sA + SWZ128((uint32_t)(row * 128 + c * 16)),
                       (const void*)(Ap + (size_t)row * IN + c * 8));
        }
#pragma unroll
        for (int it = 0; it < (TBN * 8) / NTH; it++) {
            int s = tid + it * NTH;
            int row = s >> 3, c = s & 7;
            CP_ASYNC16(sB + SWZ128((uint32_t)(row * 128 + c * 16)),
                       (const void*)(Bp + (size_t)row * IN + c * 8));
        }
    };

    const int xorv = lane & 7;
    const int a_hi = lane >> 4;
    const int b_hi = (lane >> 3) & 1;
    uint32_t a_row[MT], b_row[NT2];
#pragma unroll
    for (int mt = 0; mt < MT; mt++)
        a_row[mt] = (uint32_t)((warp_m * WM + mt * 16 + (lane & 15)) * 128);
#pragma unroll
    for (int nt2 = 0; nt2 < NT2; nt2++)
        b_row[nt2] = (uint32_t)(A_B +
                     (warp_n * WN + nt2 * 16 + ((lane & 7) | ((lane & 16) >> 1))) * 128);

    auto ldfrags = [&](uint32_t sbase, int ks, uint32_t (*af)[4], uint32_t (*bf)[4]) {
        const uint32_t ach = (uint32_t)((ks * 2 + a_hi) ^ xorv) << 4;
        const uint32_t bch = (uint32_t)((ks * 2 + b_hi) ^ xorv) << 4;
#pragma unroll
        for (int mt = 0; mt < MT; mt++)
            ldsm_x4(af[mt], sbase + a_row[mt] + ach);
#pragma unroll
        for (int nt2 = 0; nt2 < NT2; nt2++)
            ldsm_x4(bf[nt2], sbase + b_row[nt2] + bch);
    };

    float acc[MT][NT8][4] = {};
    auto mma_all = [&](uint32_t (*af)[4], uint32_t (*bf)[4]) {
#pragma unroll
        for (int mt = 0; mt < MT; mt++)
#pragma unroll
            for (int nt2 = 0; nt2 < NT2; nt2++) {
                mma16816_f16(acc[mt][nt2 * 2 + 0], af[mt], bf[nt2][0], bf[nt2][1]);
                mma16816_f16(acc[mt][nt2 * 2 + 1], af[mt], bf[nt2][2], bf[nt2][3]);
            }
    };

    uint32_t afA[MT][4], bfA[NT2][4];
    uint32_t afB[MT][4], bfB[NT2][4];

#pragma unroll
    for (int s = 0; s < NSTG - 1; s++) { load_chunk(s, s); CP_COMMIT(); }
    cp_wait<NSTG - 3>();
    __syncthreads();
    ldfrags(smem_base, 0, afA, bfA);

    for (int i = 0; i < NCH; i++) {
        const int nxt = i + NSTG - 1;
        if (nxt < NCH) load_chunk(nxt, nxt % NSTG);
        CP_COMMIT();

        const uint32_t sb_i = smem_base + (i % NSTG) * STG;
        const uint32_t sb_n = smem_base + ((i + 1) % NSTG) * STG;

        ldfrags(sb_i, 1, afB, bfB);
        mma_all(afA, bfA);
        ldfrags(sb_i, 2, afA, bfA);
        mma_all(afB, bfB);
        ldfrags(sb_i, 3, afB, bfB);
        mma_all(afA, bfA);
        ldfrags(sb_n, 0, afA, bfA);
        mma_all(afB, bfB);

        cp_wait<NSTG - 3>();
        __syncthreads();
    }
    cp_wait<0>();    // fully drain before smem reuse

    // ---- epilogue: logits(x1024) -> smem, top-2, exact fixup, dots ----
    const int qrow = lane >> 2;
    const int qcol = (lane & 3) * 2;
    constexpr int LSTR = 130;
    float* lg     = (float*)smem;                       // 64*130*4 = 33280
    int*   sidx   = (int*)(smem + 33280);
    float* sv1    = (float*)(smem + 33792);
    int*   scnt   = (int*)(smem + 34048);
    int*   scand  = (int*)(smem + 34304);
    float* sexact = (float*)(smem + 36352);

#pragma unroll
    for (int mt = 0; mt < MT; mt++)
#pragma unroll
        for (int g = 0; g < 2; g++) {
            const int r = warp_m * WM + mt * 16 + g * 8 + qrow;
#pragma unroll
            for (int nt = 0; nt < NT8; nt++) {
                const int o = warp_n * WN + nt * 8 + qcol;
                *(float2*)(lg + r * LSTR + o) =
                    make_float2(acc[mt][nt][g * 2 + 0], acc[mt][nt][g * 2 + 1]);
            }
        }
    __syncthreads();

    // top-2 per token: 4 threads per token, shfl merge
    {
        const int t = tid >> 2, sl = tid & 3;
        float v0 = -3.402823466e38f, v1 = -3.402823466e38f;
        int i0 = 0, i1 = 0;
        for (int p = sl; p < POOLS; p += 4) {
            float v = lg[t * LSTR + p];
            if (v > v0)      { v1 = v0; i1 = i0; v0 = v; i0 = p; }
            else if (v > v1) { v1 = v;  i1 = p; }
        }
#pragma unroll
        for (int off = 2; off >= 1; off >>= 1) {
            float ov0 = __shfl_down_sync(0xffffffffu, v0, off);
            float ov1 = __shfl_down_sync(0xffffffffu, v1, off);
            int   oi0 = __shfl_down_sync(0xffffffffu, i0, off);
            int   oi1 = __shfl_down_sync(0xffffffffu, i1, off);
            if (ov0 > v0) {
                float tv = v0; int ti = i0;
                v0 = ov0; i0 = oi0;
                if (tv > ov1) { v1 = tv;  i1 = ti;  }
                else          { v1 = ov1; i1 = oi1; }
            } else if (ov0 > v1) {
                v1 = ov0; i1 = oi0;
            }
        }
        if (sl == 0) {
            sidx[2 * t]     = i0;
            sidx[2 * t + 1] = i1;
            sv1[t]          = v1;
        }
    }
    __syncthreads();

    // candidate scan
    if (tid < TBM) {
        const int t = tid;
        const int i0 = sidx[2 * t], i1 = sidx[2 * t + 1];
        const float base = sv1[t] - RTHRESH;
        scand[t * 8 + 0] = i0;
        scand[t * 8 + 1] = i1;
        int n = 2;
        for (int p = 0; p < POOLS && n < 8; p++) {
            if (p == i0 || p == i1) continue;
            if (lg[t * LSTR + p] >= base) scand[t * 8 + n++] = p;
        }
        scnt[t] = n;
    }
    __syncthreads();

    // exact fp32 re-score for ambiguous tokens
    for (int t = wid * 8; t < wid * 8 + 8; t++) {
        const int n = scnt[t];
        if (n <= 2) continue;
        const float4* xr = (const float4*)(x32 + (size_t)(m0 + t) * IN);
        for (int c = 0; c < n; c++) {
            const int pool = scand[t * 8 + c];
            const float4* wp = (const float4*)(wr32 + (size_t)pool * IN);
            float a = 0.f;
            for (int i = lane; i < IN / 4; i += 32) {
                float4 xv = xr[i], wv = wp[i];
                a += xv.x * wv.x + xv.y * wv.y + xv.z * wv.z + xv.w * wv.w;
            }
#pragma unroll
            for (int off = 16; off; off >>= 1)
                a += __shfl_down_sync(0xffffffffu, a, off);
            if (lane == 0) sexact[t * 8 + c] = a;
        }
    }
    __syncthreads();

    if (tid < TBM && scnt[tid] > 2) {
        const int t = tid, n = scnt[t];
        float v0 = -3.402823466e38f, v1 = -3.402823466e38f;
        int i0 = 0, i1 = 0;
        for (int c = 0; c < n; c++) {
            float v = sexact[t * 8 + c];
            int   p = scand[t * 8 + c];
            if (v > v0)      { v1 = v0; i1 = i0; v0 = v; i0 = p; }
            else if (v > v1) { v1 = v;  i1 = p; }
        }
        sidx[2 * t]     = i0;
        sidx[2 * t + 1] = i1;
    }
    __syncthreads();

    // publish indices + dots (fp32 svh; 8 warps x 16 dots — R13 form)
    if (tid < TBM) {
        const int n = m0 + tid;
        g_idxv[2 * n]     = sidx[2 * tid];
        g_idxv[2 * n + 1] = sidx[2 * tid + 1];
    }
    for (int j = wid * 16; j < wid * 16 + 16; j++) {
        const int t = j >> 1, sel = j & 1;
        const int pool = sidx[2 * t + sel];
        const __half2* xr = (const __half2*)(g_xh + (size_t)(m0 + t) * IN);
        const float2*  sv = (const float2*)(svh + (size_t)pool * IN);
        float a0 = 0.f, a1 = 0.f;
#pragma unroll 4
        for (int i = lane; i < IN / 2; i += 64) {
            __half2 h = xr[i];          float2 s = sv[i];
            __half2 h2 = xr[i + 32];    float2 s2 = sv[i + 32];
            float2 hf = __half22float2(h);
            float2 hf2 = __half22float2(h2);
            a0 += hf.x * s.x + hf.y * s.y;
            a1 += hf2.x * s2.x + hf2.y * s2.y;
        }
        float a = a0 + a1;
#pragma unroll
        for (int off = 16; off; off >>= 1)
            a += __shfl_down_sync(0xffffffffu, a, off);
        if (lane == 0) g_dotv[2 * (m0 + t) + sel] = a;
    }

    // release: all router writes visible before count increment
    __syncthreads();
    if (tid == 0) {
        __threadfence();
        atomicAdd(&g_rtr_cnt, 1);
    }
    __syncthreads();
}

// ---------------------------------------------------------------------------
// Fused kernel: CTAs bid<128 run router phase first; ALL CTAs then run the
// main GEMM tile (BM=128, BN=256, single-term fp16). Epilogue stages u, then
// spin-waits router completion, then applies bias + rank-one combine.
// ---------------------------------------------------------------------------
__global__ void __launch_bounds__(256, 1)
fused_kernel(const float* __restrict__ b0v, const float* __restrict__ u,
             float* __restrict__ out, const float* __restrict__ x32,
             const float* __restrict__ wr32, const float* __restrict__ svh) {
    constexpr int TBM = 128, TBN = 256, NSTG = 4, NTH = 256;
    constexpr int WMN = 2, WNN = 4;
    constexpr int WM = TBM / WMN, WN = TBN / WNN;
    constexpr int MT = WM / 16, NT2 = WN / 16, NT8 = WN / 8;
    constexpr int A_B = TBM * 128, B_B = TBN * 128, STG = A_B + B_B;
    constexpr int NCH = IN / BK;

    extern __shared__ __align__(1024) char smem[];
    const uint32_t smem_base = smem_u32(smem);

    const int tid    = threadIdx.x;
    const int wid    = tid >> 5;
    const int lane   = tid & 31;
    const int warp_m = wid & 1;
    const int warp_n = wid >> 1;

    // ---- phase 1: router (first 128 CTAs; all wave-1 resident) ----
    if (blockIdx.x < RTR_CTAS)
        router_phase(smem, smem_base, blockIdx.x, x32, wr32, svh);

    // ---- phase 2: main GEMM tile ----
    constexpr int GM = 16;
    constexpr int per_group = GM * (OUT / TBN);
    const int id = blockIdx.x;
    const int m_tile = (id / per_group) * GM + (id % per_group) % GM;
    const int n_tile = (id % per_group) / GM;
    const int m0 = m_tile * TBM;
    const int n0 = n_tile * TBN;

    const uint16_t* Abase = (const uint16_t*)g_xh;
    const uint16_t* Bbase = (const uint16_t*)g_wh;

    auto load_chunk = [&](int chunk, int stage) {
        const uint16_t* Ap = Abase + (size_t)m0 * IN + chunk * BK;
        const uint16_t* Bp = Bbase + (size_t)n0 * IN + chunk * BK;
        const uint32_t sA = smem_base + stage * STG;
        const uint32_t sB = sA + A_B;
#pragma unroll
        for (int it = 0; it < (TBM * 8) / NTH; it++) {
            int s = tid + it * NTH;
            int row = s >> 3, c = s & 7;
            CP_ASYNC16(sA + SWZ128((uint32_t)(row * 128 + c * 16)),
                       (const void*)(Ap + (size_t)row * IN + c * 8));
        }
#pragma unroll
        for (int it = 0; it < (TBN * 8) / NTH; it++) {
            int s = tid + it * NTH;
            int row = s >> 3, c = s & 7;
            CP_ASYNC16(sB + SWZ128((uint32_t)(row * 128 + c * 16)),
                       (const void*)(Bp + (size_t)row * IN + c * 8));
        }
    };

    const int xorv = lane & 7;
    const int a_hi = lane >> 4;
    const int b_hi = (lane >> 3) & 1;
    uint32_t a_row[MT], b_row[NT2];
#pragma unroll
    for (int mt = 0; mt < MT; mt++)
        a_row[mt] = (uint32_t)((warp_m * WM + mt * 16 + (lane & 15)) * 128);
#pragma unroll
    for (int nt2 = 0; nt2 < NT2; nt2++)
        b_row[nt2] = (uint32_t)(A_B +
                     (warp_n * WN + nt2 * 16 + ((lane & 7) | ((lane & 16) >> 1))) * 128);

    auto ldfrags = [&](uint32_t sbase, int ks, uint32_t (*af)[4], uint32_t (*bf)[4]) {
        const uint32_t ach = (uint32_t)((ks * 2 + a_hi) ^ xorv) << 4;
        const uint32_t bch = (uint32_t)((ks * 2 + b_hi) ^ xorv) << 4;
#pragma unroll
        for (int mt = 0; mt < MT; mt++)
            ldsm_x4(af[mt], sbase + a_row[mt] + ach);
#pragma unroll
        for (int nt2 = 0; nt2 < NT2; nt2++)
            ldsm_x4(bf[nt2], sbase + b_row[nt2] + bch);
    };

    float acc[MT][NT8][4] = {};
    auto mma_all = [&](uint32_t (*af)[4], uint32_t (*bf)[4]) {
#pragma unroll
        for (int mt = 0; mt < MT; mt++)
#pragma unroll
            for (int nt2 = 0; nt2 < NT2; nt2++) {
                mma16816_f16(acc[mt][nt2 * 2 + 0], af[mt], bf[nt2][0], bf[nt2][1]);
                mma16816_f16(acc[mt][nt2 * 2 + 1], af[mt], bf[nt2][2], bf[nt2][3]);
            }
    };

    uint32_t afA[MT][4], bfA[NT2][4];
    uint32_t afB[MT][4], bfB[NT2][4];

#pragma unroll
    for (int s = 0; s < NSTG - 1; s++) { load_chunk(s, s); CP_COMMIT(); }
    cp_wait<NSTG - 3>();
    __syncthreads();
    ldfrags(smem_base, 0, afA, bfA);

    for (int i = 0; i < NCH; i++) {
        const int nxt = i + NSTG - 1;
        if (nxt < NCH) load_chunk(nxt, nxt % NSTG);
        CP_COMMIT();

        const uint32_t sb_i = smem_base + (i % NSTG) * STG;
        const uint32_t sb_n = smem_base + ((i + 1) % NSTG) * STG;

        ldfrags(sb_i, 1, afB, bfB);
        mma_all(afA, bfA);
        ldfrags(sb_i, 2, afA, bfA);
        mma_all(afB, bfB);
        ldfrags(sb_i, 3, afB, bfB);
        mma_all(afA, bfA);
        ldfrags(sb_n, 0, afA, bfA);     // next chunk ks0 (stale-safe on last)
        mma_all(afB, bfB);

        cp_wait<NSTG - 3>();
        __syncthreads();
    }

    // ---- epilogue: stage u (router-independent), wait router, combine ----
    const int qrow = lane >> 2;
    const int qcol = (lane & 3) * 2;

    float* us = (float*)smem;
    constexpr int USTR = 132;
#pragma unroll 4
    for (int idx = tid; idx < TBN * (POOLS / 4); idx += NTH) {
        int o  = idx >> 5;
        int p4 = idx & 31;
        float4 v = *(const float4*)(u + (size_t)(n0 + o) * POOLS + p4 * 4);
        *(float4*)(us + o * USTR + p4 * 4) = v;
    }

    float bo[NT8][2];
#pragma unroll
    for (int nt = 0; nt < NT8; nt++) {
        int o = n0 + warp_n * WN + nt * 8 + qcol;
        bo[nt][0] = b0v[o];
        bo[nt][1] = b0v[o + 1];
    }

    // wait for router completion (acquire)
    if (tid == 0) {
        while (*(volatile int*)&g_rtr_cnt < RTR_CTAS) { }
        __threadfence();
    }
    __syncthreads();

#pragma unroll
    for (int mt = 0; mt < MT; mt++)
#pragma unroll
        for (int g = 0; g < 2; g++) {
            const int ntok = m0 + warp_m * WM + mt * 16 + g * 8 + qrow;
            const float d0 = g_dotv[2 * ntok], d1 = g_dotv[2 * ntok + 1];
            const int   pp0 = g_idxv[2 * ntok], pp1 = g_idxv[2 * ntok + 1];
#pragma unroll
            for (int nt = 0; nt < NT8; nt++) {
                const int ol = warp_n * WN + nt * 8 + qcol;
                float v0 = acc[mt][nt][g * 2 + 0] * INV_WSCALE + bo[nt][0]
                         + d0 * us[ol * USTR + pp0]
                         + d1 * us[ol * USTR + pp1];
                float v1 = acc[mt][nt][g * 2 + 1] * INV_WSCALE + bo[nt][1]
                         + d0 * us[(ol + 1) * USTR + pp0]
                         + d1 * us[(ol + 1) * USTR + pp1];
                *(float2*)(out + (size_t)ntok * OUT + n0 + ol) = make_float2(v0, v1);
            }
        }
}

// ---------------------------------------------------------------------------
// Launch — split_w forked on stream2; split_xw (resets counter) then the
// fused router+main kernel on the main stream.
// ---------------------------------------------------------------------------
extern "C" void kernel_launch(void* const* d_in, const int* in_sizes, int n_in,
                              void* d_out, int out_size) {
    const float* x   = (const float*)d_in[0];
    const float* w0  = (const float*)d_in[1];
    const float* b0  = (const float*)d_in[2];
    const float* wr  = (const float*)d_in[3];
    const float* u   = (const float*)d_in[4];
    const float* svh = (const float*)d_in[5];
    float* out = (float*)d_out;

    constexpr int SMEM_MAIN = 4 * (128 + 256) * 128;        // 196,608 B

    cudaFuncSetAttribute((const void*)fused_kernel,
                         cudaFuncAttributeMaxDynamicSharedMemorySize, SMEM_MAIN);

    cudaStream_t s2;
    cudaEvent_t evFork, evJoin;
    bool forked = (cudaStreamCreateWithFlags(&s2, cudaStreamNonBlocking) == cudaSuccess)
               && (cudaEventCreateWithFlags(&evFork, cudaEventDisableTiming) == cudaSuccess)
               && (cudaEventCreateWithFlags(&evJoin, cudaEventDisableTiming) == cudaSuccess);

    if (forked) {
        cudaEventRecord(evFork, 0);
        cudaStreamWaitEvent(s2, evFork, 0);
        split_w_kernel<<<512, 256, 0, s2>>>((const float4*)w0);
        cudaEventRecord(evJoin, s2);

        split_xw_kernel<<<XBLK + RBLK, 256>>>((const float4*)x, (const float4*)wr);

        cudaStreamWaitEvent(0, evJoin, 0);
        fused_kernel<<<(NTOK / 128) * (OUT / 256), 256, SMEM_MAIN>>>(
            b0, u, out, x, wr, svh);
    } else {
        split_w_kernel<<<512, 256>>>((const float4*)w0);
        split_xw_kernel<<<XBLK + RBLK, 256>>>((const float4*)x, (const float4*)wr);
        fused_kernel<<<(NTOK / 128) * (OUT / 256), 256, SMEM_MAIN>>>(
            b0, u, out, x, wr, svh);
    }
}